// round 5
// baseline (speedup 1.0000x reference)
#include <cuda_runtime.h>
#include <math.h>

#define BB 2048
#define DD 1024
#define RR 64
#define HH 256

// scratch (allocation-free rule: __device__ globals)
__device__ float g_K[BB*RR];
__device__ float g_V[BB*RR];
__device__ float g_Q[BB*RR];
__device__ float g_Z[BB*RR];

// ---------------------------------------------------------------------------
// helpers
// ---------------------------------------------------------------------------
__device__ __forceinline__ float warp_allred(float v) {
#pragma unroll
    for (int o = 16; o; o >>= 1) v += __shfl_xor_sync(0xffffffffu, v, o);
    return v;
}

// tanh-approximate GELU (JAX default) + derivative
__device__ __forceinline__ float gelu_fwd(float x, float* dg) {
    const float C = 0.7978845608028654f;
    const float A = 0.044715f;
    float x2 = x * x;
    float inner = C * x * (1.0f + A * x2);
    float t = tanhf(inner);
    float half1pt = 0.5f * (1.0f + t);
    *dg = half1pt + 0.5f * x * (1.0f - t * t) * C * (1.0f + 3.0f * A * x2);
    return x * half1pt;
}

// ---------------------------------------------------------------------------
// Kernel 1: projections  K/V/Q = x @ W + b     [2048,1024] x [1024,64] x3
// BM=32, BN=64 (one weight matrix per blockIdx.y), BK=32, grid (64,3)=192 CTAs.
// Register-staged double buffering: next tile's LDGs issue before compute.
// ---------------------------------------------------------------------------
__global__ void __launch_bounds__(256) proj_kernel(
    const float* __restrict__ x,
    const float* __restrict__ Wk, const float* __restrict__ bk,
    const float* __restrict__ Wv, const float* __restrict__ bv,
    const float* __restrict__ Wq, const float* __restrict__ bq)
{
    __shared__ float As[32 * 36];   // [m][k] pad 36
    __shared__ float Bs[32 * 64];   // [k][n]

    const float* W;
    const float* bias;
    float* out;
    if (blockIdx.y == 0)      { W = Wk; bias = bk; out = g_K; }
    else if (blockIdx.y == 1) { W = Wv; bias = bv; out = g_V; }
    else                      { W = Wq; bias = bq; out = g_Q; }

    const int row0 = blockIdx.x * 32;
    const int tid = threadIdx.x;
    const int ty = tid >> 4;   // 0..15 -> 2 rows each
    const int tx = tid & 15;   // 0..15 -> 4 cols each

    // addressing for the staged loads
    const int a_m  = tid >> 3, a_k4 = tid & 7;            // A: 1 float4/thread
    const int b_k0 = tid >> 4, b_n4 = tid & 15;           // B: 2 float4/thread
    const float* a_src = x + (size_t)(row0 + a_m) * DD + a_k4 * 4;
    const float* b_src = W + (size_t)b_k0 * 64 + b_n4 * 4;

    float4 a_reg, b_reg0, b_reg1;
    // preload tile kk=0
    a_reg  = *(const float4*)(a_src);
    b_reg0 = *(const float4*)(b_src);
    b_reg1 = *(const float4*)(b_src + 16 * 64);

    float acc[2][4] = {};

    for (int kk = 0; kk < DD; kk += 32) {
        // stage current tile into smem
        *(float4*)(As + a_m * 36 + a_k4 * 4) = a_reg;
        *(float4*)(Bs + b_k0 * 64 + b_n4 * 4) = b_reg0;
        *(float4*)(Bs + (b_k0 + 16) * 64 + b_n4 * 4) = b_reg1;
        __syncthreads();

        // issue next tile's global loads (latency hidden under compute)
        if (kk + 32 < DD) {
            a_reg  = *(const float4*)(a_src + kk + 32);
            b_reg0 = *(const float4*)(b_src + (size_t)(kk + 32) * 64);
            b_reg1 = *(const float4*)(b_src + (size_t)(kk + 48) * 64);
        }

#pragma unroll
        for (int k = 0; k < 32; k++) {
            float a0 = As[(ty * 2) * 36 + k];
            float a1 = As[(ty * 2 + 1) * 36 + k];
            float4 b = *(const float4*)(Bs + k * 64 + tx * 4);
            acc[0][0] = fmaf(a0, b.x, acc[0][0]);
            acc[0][1] = fmaf(a0, b.y, acc[0][1]);
            acc[0][2] = fmaf(a0, b.z, acc[0][2]);
            acc[0][3] = fmaf(a0, b.w, acc[0][3]);
            acc[1][0] = fmaf(a1, b.x, acc[1][0]);
            acc[1][1] = fmaf(a1, b.y, acc[1][1]);
            acc[1][2] = fmaf(a1, b.z, acc[1][2]);
            acc[1][3] = fmaf(a1, b.w, acc[1][3]);
        }
        __syncthreads();
    }
    float4 bb = *(const float4*)(bias + tx * 4);
#pragma unroll
    for (int i = 0; i < 2; i++) {
        int r = row0 + ty * 2 + i;
        float4 o;
        o.x = acc[i][0] + bb.x; o.y = acc[i][1] + bb.y;
        o.z = acc[i][2] + bb.z; o.w = acc[i][3] + bb.w;
        *(float4*)(out + (size_t)r * 64 + tx * 4) = o;
    }
}

// ---------------------------------------------------------------------------
// Kernel 2: per-sample TTT core. grid=148 persistent CTAs, 256 threads.
// W1 (64x256) + W2 (256x64, row stride 65) resident in smem.
// Rank-1 gradient collapse:
//   g1 = k (x) du,  g2 = h (x) do
//   u2 = qW1 - eta*(q.k)*du,  o2 = h2W2 - eta*(h2.h)*do
// ---------------------------------------------------------------------------
__global__ void __launch_bounds__(256, 1) ttt_kernel(
    const float* __restrict__ x,
    const float* __restrict__ lrw, const float* __restrict__ lrb,
    const float* __restrict__ W1, const float* __restrict__ W2,
    const float* __restrict__ ln_g, const float* __restrict__ ln_b,
    float* __restrict__ oW1n, float* __restrict__ oW2n,
    float* __restrict__ oLoss)
{
    extern __shared__ float sm[];
    float* W1s  = sm;             // 16384  [r*256+h]
    float* W2s  = W1s + 16384;    // 16640  [h*65+r]
    float* lrws = W2s + 16640;    // 1024
    float* gs   = lrws + 1024;    // 64
    float* bls  = gs + 64;        // 64
    float* ks   = bls + 64;       // 64
    float* vs   = ks + 64;        // 64
    float* qs   = vs + 64;        // 64
    float* dos_ = qs + 64;        // 64
    float* os_  = dos_ + 64;      // 64
    float* hs   = os_ + 64;       // 256
    float* h2s  = hs + 256;       // 256
    float* dus  = h2s + 256;      // 256
    float* op   = dus + 256;      // 256
    float* red  = op + 256;       // 8
    float* scal = red + 8;        // 4

    const int tid = threadIdx.x;

    for (int i = tid; i < 16384; i += 256) W1s[i] = W1[i];
    for (int i = tid; i < 16384; i += 256) W2s[(i >> 6) * 65 + (i & 63)] = W2[i];
    for (int i = tid; i < 1024; i += 256) lrws[i] = lrw[i];
    if (tid < 64) { gs[tid] = ln_g[tid]; bls[tid] = ln_b[tid]; }
    const float lrb0 = lrb[0];
    __syncthreads();

    for (int s = blockIdx.x; s < BB; s += gridDim.x) {
        // ---------- Phase A: load k,v,q; eta; q.k ----------
        if (tid < 64) {
            ks[tid] = g_K[s * 64 + tid];
            vs[tid] = g_V[s * 64 + tid];
            qs[tid] = g_Q[s * 64 + tid];
        }
        {
            float4 xv = ((const float4*)(x + (size_t)s * DD))[tid];
            float4 lw = ((const float4*)lrws)[tid];
            float p = xv.x * lw.x + xv.y * lw.y + xv.z * lw.z + xv.w * lw.w;
            p = warp_allred(p);
            if ((tid & 31) == 0) red[tid >> 5] = p;
        }
        __syncthreads();
        if (tid == 0) {
            float t = red[0] + red[1] + red[2] + red[3] +
                      red[4] + red[5] + red[6] + red[7] + lrb0;
            scal[0] = 0.1f / (1.0f + expf(-t));   // eta
        }
        if (tid >= 32 && tid < 64) {              // warp 1: q.k
            int l = tid - 32;
            float t = ks[l] * qs[l] + ks[l + 32] * qs[l + 32];
            t = warp_allred(t);
            if (l == 0) scal[1] = t;
        }
        __syncthreads();

        // ---------- Phase B: u = kW1, uq = qW1 (shared W1 loads) ----------
        float uk = 0.0f, uq = 0.0f;
#pragma unroll
        for (int r0 = 0; r0 < 64; r0 += 8) {
            float kr[8], qr[8];
#pragma unroll
            for (int j = 0; j < 8; j++) { kr[j] = ks[r0 + j]; qr[j] = qs[r0 + j]; }
#pragma unroll
            for (int j = 0; j < 8; j++) {
                float w = W1s[(r0 + j) * 256 + tid];
                uk = fmaf(kr[j], w, uk);
                uq = fmaf(qr[j], w, uq);
            }
        }
        float gp;
        float h = gelu_fwd(uk, &gp);
        hs[tid] = h;
        __syncthreads();

        // ---------- Phase C: o = h @ W2 (4 warp-partitions over H) ----------
        {
            int part = tid >> 6, r = tid & 63;
            int h0 = part * 64;
            float acc = 0.0f;
#pragma unroll
            for (int j0 = 0; j0 < 64; j0 += 8) {
                float hv[8];
#pragma unroll
                for (int j = 0; j < 8; j++) hv[j] = hs[h0 + j0 + j];
#pragma unroll
                for (int j = 0; j < 8; j++)
                    acc = fmaf(hv[j], W2s[(h0 + j0 + j) * 65 + r], acc);
            }
            op[tid] = acc;
        }
        __syncthreads();
        if (tid < 64) os_[tid] = op[tid] + op[tid + 64] + op[tid + 128] + op[tid + 192];
        __syncthreads();

        // ---------- Phase D: LN fwd + loss + LN bwd -> do (warp 0) ----------
        if (tid < 32) {
            float o0 = os_[tid], o1 = os_[tid + 32];
            float mu = warp_allred(o0 + o1) * (1.0f / 64.0f);
            float d0 = o0 - mu, d1 = o1 - mu;
            float var = warp_allred(d0 * d0 + d1 * d1) * (1.0f / 64.0f);
            float inv = rsqrtf(var + 1e-6f);
            float n0 = d0 * inv, n1 = d1 * inv;
            float g0 = gs[tid], g1 = gs[tid + 32];
            float e0 = ks[tid] + n0 * g0 + bls[tid] - vs[tid];
            float e1 = ks[tid + 32] + n1 * g1 + bls[tid + 32] - vs[tid + 32];
            float l = warp_allred(e0 * e0 + e1 * e1) * (1.0f / 64.0f);
            if (tid == 0) oLoss[s] = l;
            float dn0 = e0 * (2.0f / 64.0f) * g0;
            float dn1 = e1 * (2.0f / 64.0f) * g1;
            float s1 = warp_allred(dn0 + dn1) * (1.0f / 64.0f);
            float s2 = warp_allred(dn0 * n0 + dn1 * n1) * (1.0f / 64.0f);
            dos_[tid]      = inv * (dn0 - s1 - n0 * s2);
            dos_[tid + 32] = inv * (dn1 - s1 - n1 * s2);
        }
        __syncthreads();

        // ---------- Phase E: dh = W2.do, du; write W2n (streaming) ----------
        const float eta = scal[0];
        float dh = 0.0f;
#pragma unroll
        for (int r0 = 0; r0 < 64; r0 += 8) {
            float dv[8];
#pragma unroll
            for (int j = 0; j < 8; j++) dv[j] = dos_[r0 + j];
#pragma unroll
            for (int j = 0; j < 8; j++)
                dh = fmaf(W2s[tid * 65 + r0 + j], dv[j], dh);
        }
        float du = dh * gp;
        dus[tid] = du;
        {
            float4* dst = (float4*)(oW2n + (size_t)s * 16384);
#pragma unroll
            for (int j = 0; j < 16; j++) {
                int idx4 = j * 256 + tid;
                int hrow = idx4 >> 4;
                int r4 = idx4 & 15;
                float c2 = eta * hs[hrow];
                float4 d4 = ((const float4*)dos_)[r4];
                const float* wr = W2s + hrow * 65 + r4 * 4;
                float4 o;
                o.x = wr[0] - c2 * d4.x; o.y = wr[1] - c2 * d4.y;
                o.z = wr[2] - c2 * d4.z; o.w = wr[3] - c2 * d4.w;
                __stcs(dst + idx4, o);   // evict-streaming: never re-read
            }
        }
        __syncthreads();   // dus complete

        // ---------- Phase F: u2 = uq - eta*(q.k)*du; h2; write W1n ----------
        {
            float qk = scal[1];
            float dgu;
            float u2 = uq - eta * qk * du;
            float h2 = gelu_fwd(u2, &dgu);
            h2s[tid] = h2;
            float hh = warp_allred(h * h2);
            if ((tid & 31) == 0) red[tid >> 5] = hh;

            float4* dst = (float4*)(oW1n + (size_t)s * 16384);
#pragma unroll
            for (int j = 0; j < 16; j++) {
                int idx4 = j * 256 + tid;
                int r = idx4 >> 6;
                int h4 = idx4 & 63;
                float c1 = eta * ks[r];
                float4 w = ((const float4*)W1s)[idx4];
                float4 d4 = ((const float4*)dus)[h4];
                float4 o;
                o.x = w.x - c1 * d4.x; o.y = w.y - c1 * d4.y;
                o.z = w.z - c1 * d4.z; o.w = w.w - c1 * d4.w;
                __stcs(dst + idx4, o);   // evict-streaming
            }
        }
        __syncthreads();   // h2s, red complete

        // ---------- Phase G: o2 = h2@W2 - eta*(h2.h)*do ----------
        {
            int part = tid >> 6, r = tid & 63;
            int h0 = part * 64;
            float acc = 0.0f;
#pragma unroll
            for (int j0 = 0; j0 < 64; j0 += 8) {
                float hv[8];
#pragma unroll
                for (int j = 0; j < 8; j++) hv[j] = h2s[h0 + j0 + j];
#pragma unroll
                for (int j = 0; j < 8; j++)
                    acc = fmaf(hv[j], W2s[(h0 + j0 + j) * 65 + r], acc);
            }
            op[tid] = acc;
        }
        __syncthreads();
        if (tid < 64) {
            float hh2 = red[0] + red[1] + red[2] + red[3] +
                        red[4] + red[5] + red[6] + red[7];
            os_[tid] = op[tid] + op[tid + 64] + op[tid + 128] + op[tid + 192]
                       - eta * hh2 * dos_[tid];
        }
        __syncthreads();

        // ---------- Phase H: z = q + LN(o2) ----------
        if (tid < 32) {
            float o0 = os_[tid], o1 = os_[tid + 32];
            float mu = warp_allred(o0 + o1) * (1.0f / 64.0f);
            float d0 = o0 - mu, d1 = o1 - mu;
            float var = warp_allred(d0 * d0 + d1 * d1) * (1.0f / 64.0f);
            float inv = rsqrtf(var + 1e-6f);
            g_Z[s * 64 + tid]      = qs[tid]      + d0 * inv * gs[tid]      + bls[tid];
            g_Z[s * 64 + tid + 32] = qs[tid + 32] + d1 * inv * gs[tid + 32] + bls[tid + 32];
        }
        __syncthreads();
    }
}

// ---------------------------------------------------------------------------
// Kernel 3: out = z @ Wo + bo   [2048,64] x [64,1024]
// BM=64, BN=128, K=64 single tile. 256 threads, 8x4 microtile.
// ---------------------------------------------------------------------------
__global__ void __launch_bounds__(256) out_kernel(
    const float* __restrict__ Wo, const float* __restrict__ bo,
    float* __restrict__ out)
{
    __shared__ float Zs[64 * 64];     // 16 KB
    __shared__ float Wos[64 * 128];   // 32 KB

    const int row0 = blockIdx.x * 64;
    const int col0 = blockIdx.y * 128;
    const int tid = threadIdx.x;

#pragma unroll
    for (int i = 0; i < 4; i++) {
        int idx4 = tid + i * 256;
        *(float4*)(Zs + idx4 * 4) =
            *(const float4*)(g_Z + (size_t)row0 * 64 + idx4 * 4);
    }
#pragma unroll
    for (int i = 0; i < 8; i++) {
        int idx4 = tid + i * 256;
        int k = idx4 >> 5, n4 = idx4 & 31;
        *(float4*)(Wos + k * 128 + n4 * 4) =
            *(const float4*)(Wo + (size_t)k * DD + col0 + n4 * 4);
    }
    __syncthreads();

    const int ty = tid >> 5;    // 0..7 -> 8 rows each
    const int lane = tid & 31;  // 4 cols each
    float acc[8][4] = {};

#pragma unroll
    for (int k0 = 0; k0 < 64; k0 += 4) {
        float4 av[8];
#pragma unroll
        for (int i = 0; i < 8; i++)
            av[i] = *(const float4*)(Zs + (ty * 8 + i) * 64 + k0);
#pragma unroll
        for (int kk = 0; kk < 4; kk++) {
            float4 b = *(const float4*)(Wos + (k0 + kk) * 128 + lane * 4);
#pragma unroll
            for (int i = 0; i < 8; i++) {
                float a = (kk == 0) ? av[i].x : (kk == 1) ? av[i].y
                          : (kk == 2) ? av[i].z : av[i].w;
                acc[i][0] = fmaf(a, b.x, acc[i][0]);
                acc[i][1] = fmaf(a, b.y, acc[i][1]);
                acc[i][2] = fmaf(a, b.z, acc[i][2]);
                acc[i][3] = fmaf(a, b.w, acc[i][3]);
            }
        }
    }

    float4 bb = *(const float4*)(bo + col0 + lane * 4);
#pragma unroll
    for (int i = 0; i < 8; i++) {
        float4 o;
        o.x = acc[i][0] + bb.x; o.y = acc[i][1] + bb.y;
        o.z = acc[i][2] + bb.z; o.w = acc[i][3] + bb.w;
        __stcs((float4*)(out + (size_t)(row0 + ty * 8 + i) * DD + col0 + lane * 4), o);
    }
}

// ---------------------------------------------------------------------------
// launch
// ---------------------------------------------------------------------------
extern "C" void kernel_launch(void* const* d_in, const int* in_sizes, int n_in,
                              void* d_out, int out_size)
{
    const float* x    = (const float*)d_in[0];
    const float* Wk   = (const float*)d_in[1];
    const float* bk   = (const float*)d_in[2];
    const float* Wv   = (const float*)d_in[3];
    const float* bv   = (const float*)d_in[4];
    const float* Wq   = (const float*)d_in[5];
    const float* bq   = (const float*)d_in[6];
    const float* Wo   = (const float*)d_in[7];
    const float* bo   = (const float*)d_in[8];
    const float* ln_g = (const float*)d_in[9];
    const float* ln_b = (const float*)d_in[10];
    const float* lrw  = (const float*)d_in[11];
    const float* lrb  = (const float*)d_in[12];
    const float* W1   = (const float*)d_in[13];
    const float* W2   = (const float*)d_in[14];

    float* out = (float*)d_out;
    float* oOut  = out;                          // 2048*1024
    float* oW1n  = out + (size_t)2097152;        // 2048*64*256
    float* oW2n  = oW1n + (size_t)33554432;      // 2048*256*64
    float* oLoss = oW2n + (size_t)33554432;      // 2048

    const int ttt_smem = 35532 * 4;  // 142128 bytes
    cudaFuncSetAttribute(ttt_kernel,
                         cudaFuncAttributeMaxDynamicSharedMemorySize, ttt_smem);

    proj_kernel<<<dim3(64, 3), 256>>>(x, Wk, bk, Wv, bv, Wq, bq);
    ttt_kernel<<<148, 256, ttt_smem>>>(x, lrw, lrb, W1, W2, ln_g, ln_b,
                                       oW1n, oW2n, oLoss);
    out_kernel<<<dim3(32, 8), 256>>>(Wo, bo, oOut);
}

// round 15
// speedup vs baseline: 1.1262x; 1.1262x over previous
#include <cuda_runtime.h>
#include <math.h>

#define BB 2048
#define DD 1024
#define RR 64
#define HH 256

// scratch (allocation-free rule: __device__ globals)
// g_P[proj][kpart][s*64+r] : split-K partials for K/V/Q projections
__device__ float g_P[3][4][BB*RR];
__device__ float g_Z[BB*RR];

// ---------------------------------------------------------------------------
// helpers
// ---------------------------------------------------------------------------
__device__ __forceinline__ float warp_allred(float v) {
#pragma unroll
    for (int o = 16; o; o >>= 1) v += __shfl_xor_sync(0xffffffffu, v, o);
    return v;
}

// tanh-approximate GELU (JAX default) + derivative
__device__ __forceinline__ float gelu_fwd(float x, float* dg) {
    const float C = 0.7978845608028654f;
    const float A = 0.044715f;
    float x2 = x * x;
    float inner = C * x * (1.0f + A * x2);
    float t = tanhf(inner);
    float half1pt = 0.5f * (1.0f + t);
    *dg = half1pt + 0.5f * x * (1.0f - t * t) * C * (1.0f + 3.0f * A * x2);
    return x * half1pt;
}

// ---------------------------------------------------------------------------
// Kernel 1: projections, split-K x4.
// grid (64 m-tiles, 3 proj, 4 k-parts) = 768 CTAs -> 4 CTAs/SM (reg-capped),
// ~32 warps/SM. Each CTA: BM=32, BN=64, K=256. Register-staged double buffer.
// Partials summed by ttt_kernel Phase A. Bias added by part 0 only.
// ---------------------------------------------------------------------------
__global__ void __launch_bounds__(256) proj_kernel(
    const float* __restrict__ x,
    const float* __restrict__ Wk, const float* __restrict__ bk,
    const float* __restrict__ Wv, const float* __restrict__ bv,
    const float* __restrict__ Wq, const float* __restrict__ bq)
{
    __shared__ float As[32 * 36];   // [m][k] pad 36
    __shared__ float Bs[32 * 64];   // [k][n]

    const float* W;
    const float* bias;
    if (blockIdx.y == 0)      { W = Wk; bias = bk; }
    else if (blockIdx.y == 1) { W = Wv; bias = bv; }
    else                      { W = Wq; bias = bq; }
    float* out = &g_P[blockIdx.y][blockIdx.z][0];

    const int row0   = blockIdx.x * 32;
    const int k_base = blockIdx.z * 256;
    const int tid = threadIdx.x;
    const int ty = tid >> 4;   // 0..15 -> 2 rows each
    const int tx = tid & 15;   // 0..15 -> 4 cols each

    // addressing for the staged loads
    const int a_m  = tid >> 3, a_k4 = tid & 7;            // A: 1 float4/thread
    const int b_k0 = tid >> 4, b_n4 = tid & 15;           // B: 2 float4/thread
    const float* a_src = x + (size_t)(row0 + a_m) * DD + k_base + a_k4 * 4;
    const float* b_src = W + (size_t)(k_base + b_k0) * 64 + b_n4 * 4;

    float4 a_reg, b_reg0, b_reg1;
    // preload first tile of this K-quarter
    a_reg  = *(const float4*)(a_src);
    b_reg0 = *(const float4*)(b_src);
    b_reg1 = *(const float4*)(b_src + 16 * 64);

    float acc[2][4] = {};

    for (int kk = 0; kk < 256; kk += 32) {
        // stage current tile into smem
        *(float4*)(As + a_m * 36 + a_k4 * 4) = a_reg;
        *(float4*)(Bs + b_k0 * 64 + b_n4 * 4) = b_reg0;
        *(float4*)(Bs + (b_k0 + 16) * 64 + b_n4 * 4) = b_reg1;
        __syncthreads();

        // issue next tile's global loads (latency hidden under compute)
        if (kk + 32 < 256) {
            a_reg  = *(const float4*)(a_src + kk + 32);
            b_reg0 = *(const float4*)(b_src + (size_t)(kk + 32) * 64);
            b_reg1 = *(const float4*)(b_src + (size_t)(kk + 48) * 64);
        }

#pragma unroll
        for (int k = 0; k < 32; k++) {
            float a0 = As[(ty * 2) * 36 + k];
            float a1 = As[(ty * 2 + 1) * 36 + k];
            float4 b = *(const float4*)(Bs + k * 64 + tx * 4);
            acc[0][0] = fmaf(a0, b.x, acc[0][0]);
            acc[0][1] = fmaf(a0, b.y, acc[0][1]);
            acc[0][2] = fmaf(a0, b.z, acc[0][2]);
            acc[0][3] = fmaf(a0, b.w, acc[0][3]);
            acc[1][0] = fmaf(a1, b.x, acc[1][0]);
            acc[1][1] = fmaf(a1, b.y, acc[1][1]);
            acc[1][2] = fmaf(a1, b.z, acc[1][2]);
            acc[1][3] = fmaf(a1, b.w, acc[1][3]);
        }
        __syncthreads();
    }
    float4 bb;
    if (blockIdx.z == 0) bb = *(const float4*)(bias + tx * 4);
    else                 bb = make_float4(0.f, 0.f, 0.f, 0.f);
#pragma unroll
    for (int i = 0; i < 2; i++) {
        int r = row0 + ty * 2 + i;
        float4 o;
        o.x = acc[i][0] + bb.x; o.y = acc[i][1] + bb.y;
        o.z = acc[i][2] + bb.z; o.w = acc[i][3] + bb.w;
        *(float4*)(out + (size_t)r * 64 + tx * 4) = o;
    }
}

// ---------------------------------------------------------------------------
// Kernel 2: per-sample TTT core. 148 persistent CTAs, 1024 threads,
// FOUR samples per CTA iteration (slot = tid>>8). W1/W2 smem shared read-only.
// Rank-1 gradient collapse:
//   g1 = k (x) du,  g2 = h (x) do
//   u2 = qW1 - eta*(q.k)*du,  o2 = h2W2 - eta*(h2.h)*do
// ---------------------------------------------------------------------------
#define SLOT_F 1360   // floats per per-sample buffer block
#define NSLOT 4

__global__ void __launch_bounds__(1024, 1) ttt_kernel(
    const float* __restrict__ x,
    const float* __restrict__ lrw, const float* __restrict__ lrb,
    const float* __restrict__ W1, const float* __restrict__ W2,
    const float* __restrict__ ln_g, const float* __restrict__ ln_b,
    float* __restrict__ oW1n, float* __restrict__ oW2n,
    float* __restrict__ oLoss)
{
    extern __shared__ float sm[];
    float* W1s  = sm;             // 16384  [r*256+h]
    float* W2s  = W1s + 16384;    // 16640  [h*65+r]
    float* lrws = W2s + 16640;    // 1024
    float* gs   = lrws + 1024;    // 64
    float* bls  = gs + 64;        // 64
    float* slot0 = bls + 64;      // NSLOT x SLOT_F

    const int tid  = threadIdx.x;
    const int slot = tid >> 8;    // 0..3
    const int t    = tid & 255;   // thread within slot

    float* sb   = slot0 + slot * SLOT_F;
    float* ks   = sb;             // 64
    float* vs   = sb + 64;        // 64
    float* qs   = sb + 128;       // 64
    float* dos_ = sb + 192;       // 64
    float* os_  = sb + 256;       // 64
    float* hs   = sb + 320;       // 256
    float* h2s  = sb + 576;       // 256
    float* dus  = sb + 832;       // 256
    float* op   = sb + 1088;      // 256
    float* red  = sb + 1344;      // 8
    float* scal = sb + 1352;      // 4 (+4 pad)

    for (int i = tid; i < 16384; i += 1024) W1s[i] = W1[i];
    for (int i = tid; i < 16384; i += 1024) W2s[(i >> 6) * 65 + (i & 63)] = W2[i];
    for (int i = tid; i < 1024; i += 1024) lrws[i] = lrw[i];
    if (tid < 64) { gs[tid] = ln_g[tid]; bls[tid] = ln_b[tid]; }
    const float lrb0 = lrb[0];
    __syncthreads();

    for (int sbase = blockIdx.x * NSLOT; sbase < BB; sbase += gridDim.x * NSLOT) {
        const int s = sbase + slot;   // BB % NSLOT == 0 -> always < BB

        // ---------- Phase A: load k,v,q (sum split-K partials); eta; q.k ----
        if (t < 64) {
            int idx = s * 64 + t;
            ks[t] = g_P[0][0][idx] + g_P[0][1][idx] + g_P[0][2][idx] + g_P[0][3][idx];
            vs[t] = g_P[1][0][idx] + g_P[1][1][idx] + g_P[1][2][idx] + g_P[1][3][idx];
            qs[t] = g_P[2][0][idx] + g_P[2][1][idx] + g_P[2][2][idx] + g_P[2][3][idx];
        }
        {
            float4 xv = ((const float4*)(x + (size_t)s * DD))[t];
            float4 lw = ((const float4*)lrws)[t];
            float p = xv.x * lw.x + xv.y * lw.y + xv.z * lw.z + xv.w * lw.w;
            p = warp_allred(p);
            if ((t & 31) == 0) red[t >> 5] = p;
        }
        __syncthreads();
        if (t == 0) {
            float tt = red[0] + red[1] + red[2] + red[3] +
                       red[4] + red[5] + red[6] + red[7] + lrb0;
            scal[0] = 0.1f / (1.0f + expf(-tt));   // eta
        }
        if (t >= 32 && t < 64) {                   // warp 1 of slot: q.k
            int l = t - 32;
            float tt = ks[l] * qs[l] + ks[l + 32] * qs[l + 32];
            tt = warp_allred(tt);
            if (l == 0) scal[1] = tt;
        }
        __syncthreads();

        // ---------- Phase B: u = kW1, uq = qW1 (shared W1 loads) ----------
        float uk = 0.0f, uq = 0.0f;
#pragma unroll
        for (int r0 = 0; r0 < 64; r0 += 8) {
            float kr[8], qr[8];
#pragma unroll
            for (int j = 0; j < 8; j++) { kr[j] = ks[r0 + j]; qr[j] = qs[r0 + j]; }
#pragma unroll
            for (int j = 0; j < 8; j++) {
                float w = W1s[(r0 + j) * 256 + t];
                uk = fmaf(kr[j], w, uk);
                uq = fmaf(qr[j], w, uq);
            }
        }
        float gp;
        float h = gelu_fwd(uk, &gp);
        hs[t] = h;
        __syncthreads();

        // ---------- Phase C: o = h @ W2 (4 warp-partitions over H) ----------
        {
            int part = t >> 6, r = t & 63;
            int h0 = part * 64;
            float acc = 0.0f;
#pragma unroll
            for (int j0 = 0; j0 < 64; j0 += 8) {
                float hv[8];
#pragma unroll
                for (int j = 0; j < 8; j++) hv[j] = hs[h0 + j0 + j];
#pragma unroll
                for (int j = 0; j < 8; j++)
                    acc = fmaf(hv[j], W2s[(h0 + j0 + j) * 65 + r], acc);
            }
            op[t] = acc;
        }
        __syncthreads();
        if (t < 64) os_[t] = op[t] + op[t + 64] + op[t + 128] + op[t + 192];
        __syncthreads();

        // ---------- Phase D: LN fwd + loss + LN bwd -> do (warp 0/slot) ----
        if (t < 32) {
            float o0 = os_[t], o1 = os_[t + 32];
            float mu = warp_allred(o0 + o1) * (1.0f / 64.0f);
            float d0 = o0 - mu, d1 = o1 - mu;
            float var = warp_allred(d0 * d0 + d1 * d1) * (1.0f / 64.0f);
            float inv = rsqrtf(var + 1e-6f);
            float n0 = d0 * inv, n1 = d1 * inv;
            float g0 = gs[t], g1 = gs[t + 32];
            float e0 = ks[t] + n0 * g0 + bls[t] - vs[t];
            float e1 = ks[t + 32] + n1 * g1 + bls[t + 32] - vs[t + 32];
            float l = warp_allred(e0 * e0 + e1 * e1) * (1.0f / 64.0f);
            if (t == 0) oLoss[s] = l;
            float dn0 = e0 * (2.0f / 64.0f) * g0;
            float dn1 = e1 * (2.0f / 64.0f) * g1;
            float s1 = warp_allred(dn0 + dn1) * (1.0f / 64.0f);
            float s2 = warp_allred(dn0 * n0 + dn1 * n1) * (1.0f / 64.0f);
            dos_[t]      = inv * (dn0 - s1 - n0 * s2);
            dos_[t + 32] = inv * (dn1 - s1 - n1 * s2);
        }
        __syncthreads();

        // ---------- Phase E: dh = W2.do, du; write W2n (streaming) ----------
        const float eta = scal[0];
        float dh = 0.0f;
#pragma unroll
        for (int r0 = 0; r0 < 64; r0 += 8) {
            float dv[8];
#pragma unroll
            for (int j = 0; j < 8; j++) dv[j] = dos_[r0 + j];
#pragma unroll
            for (int j = 0; j < 8; j++)
                dh = fmaf(W2s[t * 65 + r0 + j], dv[j], dh);
        }
        float du = dh * gp;
        dus[t] = du;
        {
            float4* dst = (float4*)(oW2n + (size_t)s * 16384);
#pragma unroll
            for (int j = 0; j < 16; j++) {
                int idx4 = j * 256 + t;
                int hrow = idx4 >> 4;
                int r4 = idx4 & 15;
                float c2 = eta * hs[hrow];
                float4 d4 = ((const float4*)dos_)[r4];
                const float* wr = W2s + hrow * 65 + r4 * 4;
                float4 o;
                o.x = wr[0] - c2 * d4.x; o.y = wr[1] - c2 * d4.y;
                o.z = wr[2] - c2 * d4.z; o.w = wr[3] - c2 * d4.w;
                __stcs(dst + idx4, o);   // evict-streaming: never re-read
            }
        }
        __syncthreads();   // dus complete

        // ---------- Phase F: u2 = uq - eta*(q.k)*du; h2; write W1n ----------
        {
            float qk = scal[1];
            float dgu;
            float u2 = uq - eta * qk * du;
            float h2 = gelu_fwd(u2, &dgu);
            h2s[t] = h2;
            float hh = warp_allred(h * h2);
            if ((t & 31) == 0) red[t >> 5] = hh;

            float4* dst = (float4*)(oW1n + (size_t)s * 16384);
#pragma unroll
            for (int j = 0; j < 16; j++) {
                int idx4 = j * 256 + t;
                int r = idx4 >> 6;
                int h4 = idx4 & 63;
                float c1 = eta * ks[r];
                float4 w = ((const float4*)W1s)[idx4];
                float4 d4 = ((const float4*)dus)[h4];
                float4 o;
                o.x = w.x - c1 * d4.x; o.y = w.y - c1 * d4.y;
                o.z = w.z - c1 * d4.z; o.w = w.w - c1 * d4.w;
                __stcs(dst + idx4, o);   // evict-streaming
            }
        }
        __syncthreads();   // h2s, red complete

        // ---------- Phase G: o2 = h2@W2 - eta*(h2.h)*do ----------
        {
            int part = t >> 6, r = t & 63;
            int h0 = part * 64;
            float acc = 0.0f;
#pragma unroll
            for (int j0 = 0; j0 < 64; j0 += 8) {
                float hv[8];
#pragma unroll
                for (int j = 0; j < 8; j++) hv[j] = h2s[h0 + j0 + j];
#pragma unroll
                for (int j = 0; j < 8; j++)
                    acc = fmaf(hv[j], W2s[(h0 + j0 + j) * 65 + r], acc);
            }
            op[t] = acc;
        }
        __syncthreads();
        if (t < 64) {
            float hh2 = red[0] + red[1] + red[2] + red[3] +
                        red[4] + red[5] + red[6] + red[7];
            os_[t] = op[t] + op[t + 64] + op[t + 128] + op[t + 192]
                     - eta * hh2 * dos_[t];
        }
        __syncthreads();

        // ---------- Phase H: z = q + LN(o2) ----------
        if (t < 32) {
            float o0 = os_[t], o1 = os_[t + 32];
            float mu = warp_allred(o0 + o1) * (1.0f / 64.0f);
            float d0 = o0 - mu, d1 = o1 - mu;
            float var = warp_allred(d0 * d0 + d1 * d1) * (1.0f / 64.0f);
            float inv = rsqrtf(var + 1e-6f);
            g_Z[s * 64 + t]      = qs[t]      + d0 * inv * gs[t]      + bls[t];
            g_Z[s * 64 + t + 32] = qs[t + 32] + d1 * inv * gs[t + 32] + bls[t + 32];
        }
        __syncthreads();
    }
}

// ---------------------------------------------------------------------------
// Kernel 3: out = z @ Wo + bo   [2048,64] x [64,1024]
// BM=64, BN=128, K=64 single tile. 256 threads, 8x4 microtile.
// ---------------------------------------------------------------------------
__global__ void __launch_bounds__(256) out_kernel(
    const float* __restrict__ Wo, const float* __restrict__ bo,
    float* __restrict__ out)
{
    __shared__ float Zs[64 * 64];     // 16 KB
    __shared__ float Wos[64 * 128];   // 32 KB

    const int row0 = blockIdx.x * 64;
    const int col0 = blockIdx.y * 128;
    const int tid = threadIdx.x;

#pragma unroll
    for (int i = 0; i < 4; i++) {
        int idx4 = tid + i * 256;
        *(float4*)(Zs + idx4 * 4) =
            *(const float4*)(g_Z + (size_t)row0 * 64 + idx4 * 4);
    }
#pragma unroll
    for (int i = 0; i < 8; i++) {
        int idx4 = tid + i * 256;
        int k = idx4 >> 5, n4 = idx4 & 31;
        *(float4*)(Wos + k * 128 + n4 * 4) =
            *(const float4*)(Wo + (size_t)k * DD + col0 + n4 * 4);
    }
    __syncthreads();

    const int ty = tid >> 5;    // 0..7 -> 8 rows each
    const int lane = tid & 31;  // 4 cols each
    float acc[8][4] = {};

#pragma unroll
    for (int k0 = 0; k0 < 64; k0 += 4) {
        float4 av[8];
#pragma unroll
        for (int i = 0; i < 8; i++)
            av[i] = *(const float4*)(Zs + (ty * 8 + i) * 64 + k0);
#pragma unroll
        for (int kk = 0; kk < 4; kk++) {
            float4 b = *(const float4*)(Wos + (k0 + kk) * 128 + lane * 4);
#pragma unroll
            for (int i = 0; i < 8; i++) {
                float a = (kk == 0) ? av[i].x : (kk == 1) ? av[i].y
                          : (kk == 2) ? av[i].z : av[i].w;
                acc[i][0] = fmaf(a, b.x, acc[i][0]);
                acc[i][1] = fmaf(a, b.y, acc[i][1]);
                acc[i][2] = fmaf(a, b.z, acc[i][2]);
                acc[i][3] = fmaf(a, b.w, acc[i][3]);
            }
        }
    }

    float4 bb = *(const float4*)(bo + col0 + lane * 4);
#pragma unroll
    for (int i = 0; i < 8; i++) {
        float4 o;
        o.x = acc[i][0] + bb.x; o.y = acc[i][1] + bb.y;
        o.z = acc[i][2] + bb.z; o.w = acc[i][3] + bb.w;
        __stcs((float4*)(out + (size_t)(row0 + ty * 8 + i) * DD + col0 + lane * 4), o);
    }
}

// ---------------------------------------------------------------------------
// launch
// ---------------------------------------------------------------------------
extern "C" void kernel_launch(void* const* d_in, const int* in_sizes, int n_in,
                              void* d_out, int out_size)
{
    const float* x    = (const float*)d_in[0];
    const float* Wk   = (const float*)d_in[1];
    const float* bk   = (const float*)d_in[2];
    const float* Wv   = (const float*)d_in[3];
    const float* bv   = (const float*)d_in[4];
    const float* Wq   = (const float*)d_in[5];
    const float* bq   = (const float*)d_in[6];
    const float* Wo   = (const float*)d_in[7];
    const float* bo   = (const float*)d_in[8];
    const float* ln_g = (const float*)d_in[9];
    const float* ln_b = (const float*)d_in[10];
    const float* lrw  = (const float*)d_in[11];
    const float* lrb  = (const float*)d_in[12];
    const float* W1   = (const float*)d_in[13];
    const float* W2   = (const float*)d_in[14];

    float* out = (float*)d_out;
    float* oOut  = out;                          // 2048*1024
    float* oW1n  = out + (size_t)2097152;        // 2048*64*256
    float* oW2n  = oW1n + (size_t)33554432;      // 2048*256*64
    float* oLoss = oW2n + (size_t)33554432;      // 2048

    // smem: 16384+16640+1024+64+64 + 4*1360 = 39616 floats
    const int ttt_smem = 39616 * 4;  // 158464 bytes
    cudaFuncSetAttribute(ttt_kernel,
                         cudaFuncAttributeMaxDynamicSharedMemorySize, ttt_smem);

    proj_kernel<<<dim3(64, 3, 4), 256>>>(x, Wk, bk, Wv, bv, Wq, bq);
    ttt_kernel<<<148, 1024, ttt_smem>>>(x, lrw, lrb, W1, W2, ln_g, ln_b,
                                        oW1n, oW2n, oLoss);
    out_kernel<<<dim3(32, 8), 256>>>(Wo, bo, oOut);
}